// round 2
// baseline (speedup 1.0000x reference)
#include <cuda_runtime.h>
#include <math.h>

// ---------------- problem constants (fixed by reference) ----------------
constexpr int   Bb   = 2;
constexpr int   Ss   = 2048;
constexpr int   Ee   = 1024;
constexpr int   Hh   = 16;
constexpr int   Dd   = 64;      // E / H
constexpr int   Ff   = 4096;    // 4*E
constexpr int   Mtok = Bb * Ss; // 4096 tokens
constexpr float EPSc  = 1e-5f;
constexpr float SCALE = 0.125f; // D^-0.5

// ---------------- scratch (static device globals; no runtime alloc) ----
__device__ float g_nx  [(size_t)Mtok * Ee];
__device__ float g_q   [(size_t)Mtok * Ee];   // [B,H,S,D]
__device__ float g_k   [(size_t)Mtok * Ee];   // [B,H,S,D]
__device__ float g_v   [(size_t)Mtok * Ee];   // [B,H,S,D]
__device__ float g_vals[(size_t)Mtok * Ee];   // [B,S,E]
__device__ float g_x1  [(size_t)Mtok * Ee];   // attn residual output
__device__ float g_h   [(size_t)Mtok * Ff];   // FFN hidden
__device__ float g_scores[(size_t)Bb * Hh * Ss * Ss]; // 512 MiB

// ---------------- reductions ----------------
__device__ __forceinline__ float warpSum(float v) {
    #pragma unroll
    for (int o = 16; o; o >>= 1) v += __shfl_xor_sync(0xFFFFFFFFu, v, o);
    return v;
}
__device__ __forceinline__ float warpMax(float v) {
    #pragma unroll
    for (int o = 16; o; o >>= 1) v = fmaxf(v, __shfl_xor_sync(0xFFFFFFFFu, v, o));
    return v;
}
// blockDim.x == 256 assumed. Returns broadcast value.
__device__ __forceinline__ float blockSum(float v, float* sh, float* bc) {
    int lane = threadIdx.x & 31, wid = threadIdx.x >> 5;
    v = warpSum(v);
    if (!lane) sh[wid] = v;
    __syncthreads();
    if (wid == 0) {
        v = (lane < 8) ? sh[lane] : 0.f;
        v = warpSum(v);
        if (!lane) *bc = v;
    }
    __syncthreads();
    return *bc;
}
__device__ __forceinline__ float blockMax(float v, float* sh, float* bc) {
    int lane = threadIdx.x & 31, wid = threadIdx.x >> 5;
    v = warpMax(v);
    if (!lane) sh[wid] = v;
    __syncthreads();
    if (wid == 0) {
        v = (lane < 8) ? sh[lane] : -3.4e38f;
        v = warpMax(v);
        if (!lane) *bc = v;
    }
    __syncthreads();
    return *bc;
}

// ---------------- LayerNorm (matches reference: unbiased var, /(std+eps)) ----
__global__ void ln_kernel(const float* __restrict__ x, const float* __restrict__ w,
                          const float* __restrict__ b, float* __restrict__ out)
{
    __shared__ float sh[32];
    __shared__ float bc;
    const int row = blockIdx.x, t = threadIdx.x;
    float4 v = *(const float4*)(x + (size_t)row * Ee + t * 4);
    float mean = blockSum(v.x + v.y + v.z + v.w, sh, &bc) * (1.f / Ee);
    float dx0 = v.x - mean, dx1 = v.y - mean, dx2 = v.z - mean, dx3 = v.w - mean;
    float var = blockSum(dx0*dx0 + dx1*dx1 + dx2*dx2 + dx3*dx3, sh, &bc) * (1.f / (Ee - 1));
    float r = 1.f / (sqrtf(var) + EPSc);
    float4 wv = *(const float4*)(w + t * 4);
    float4 bv = *(const float4*)(b + t * 4);
    float4 o;
    o.x = wv.x * dx0 * r + bv.x;
    o.y = wv.y * dx1 * r + bv.y;
    o.z = wv.z * dx2 * r + bv.z;
    o.w = wv.w * dx3 * r + bv.w;
    *(float4*)(out + (size_t)row * Ee + t * 4) = o;
}

// ---------------- softmax over S=2048, with scale + mask, in place -----
__global__ void softmax_kernel(float* __restrict__ sc, const int* __restrict__ mask)
{
    __shared__ float sh[32];
    __shared__ float bc;
    const size_t row = blockIdx.x;               // over B*H*S rows
    const int t = threadIdx.x;
    float* p = sc + row * (size_t)Ss;
    const int b_ = (int)(row / ((size_t)Hh * Ss));
    const int s_ = (int)(row % Ss);
    const int* mrow = mask + ((size_t)b_ * Ss + s_) * Ss;

    float v[8];
    #pragma unroll
    for (int u = 0; u < 2; u++) {
        int idx = u * 1024 + t * 4;
        float4 sv = *(const float4*)(p + idx);
        int4   mv = *(const int4*)(mrow + idx);
        v[u*4+0] = mv.x ? sv.x * SCALE : -INFINITY;
        v[u*4+1] = mv.y ? sv.y * SCALE : -INFINITY;
        v[u*4+2] = mv.z ? sv.z * SCALE : -INFINITY;
        v[u*4+3] = mv.w ? sv.w * SCALE : -INFINITY;
    }
    float mx = v[0];
    #pragma unroll
    for (int i = 1; i < 8; i++) mx = fmaxf(mx, v[i]);
    mx = blockMax(mx, sh, &bc);
    float sum = 0.f;
    #pragma unroll
    for (int i = 0; i < 8; i++) { v[i] = __expf(v[i] - mx); sum += v[i]; }
    sum = blockSum(sum, sh, &bc);
    float inv = 1.f / sum;
    #pragma unroll
    for (int u = 0; u < 2; u++) {
        int idx = u * 1024 + t * 4;
        float4 o = make_float4(v[u*4+0]*inv, v[u*4+1]*inv, v[u*4+2]*inv, v[u*4+3]*inv);
        *(float4*)(p + idx) = o;
    }
}

// ---------------- GEMM: C = A @ op(B) (+bias)(+relu)(+residual) ---------
// TRANSB=true : B is [N,K] row-major (weights, contraction over K)  -> C[m,n]=sum A[m,k]*B[n,k]
// TRANSB=false: B is [K,N] row-major                                 -> C[m,n]=sum A[m,k]*B[k,n]
// EPI: 0=plain(+bias if nonnull), 1=bias+relu, 2=bias+residual,
//      3=bias + scatter to q/k/v [B,H,S,D], 4=scatter vals to [B,S,E] (no bias)
// Requires: M%128==0, N%BN==0, K%8==0, grid exact.
template<bool TRANSB, int EPI, int BN, int TN>
__global__ __launch_bounds__(256)
void gemm_kernel(const float* __restrict__ A, const float* __restrict__ Bm,
                 const float* __restrict__ bias, const float* __restrict__ Res,
                 float* __restrict__ C,
                 int M, int N, int K, size_t sA, size_t sB, size_t sC)
{
    constexpr int BM = 128, BK = 8, TM = 8;
    const int bz = blockIdx.z;
    A  += (size_t)bz * sA;
    Bm += (size_t)bz * sB;
    C  += (size_t)bz * sC;

    __shared__ float As[BK][BM + 4];
    __shared__ float Bs[BK][BN + 4];

    const int t  = threadIdx.x;
    const int tx = t % (BN / TN);
    const int ty = t / (BN / TN);
    const int rowBase = blockIdx.y * BM;
    const int colBase = blockIdx.x * BN;

    float acc[TM][TN];
    #pragma unroll
    for (int i = 0; i < TM; i++)
        #pragma unroll
        for (int j = 0; j < TN; j++) acc[i][j] = 0.f;

    for (int k0 = 0; k0 < K; k0 += BK) {
        { // A tile: [BM rows, BK cols] -> As[k][m]
            int r = t >> 1, c4 = (t & 1) * 4;
            float4 av = *(const float4*)(A + (size_t)(rowBase + r) * K + k0 + c4);
            As[c4+0][r] = av.x; As[c4+1][r] = av.y; As[c4+2][r] = av.z; As[c4+3][r] = av.w;
        }
        if constexpr (TRANSB) { // weights [N,K]: tile [BN rows, BK cols] -> Bs[k][n]; BN==128
            int n = t >> 1, c4 = (t & 1) * 4;
            float4 bv = *(const float4*)(Bm + (size_t)(colBase + n) * K + k0 + c4);
            Bs[c4+0][n] = bv.x; Bs[c4+1][n] = bv.y; Bs[c4+2][n] = bv.z; Bs[c4+3][n] = bv.w;
        } else {
            if constexpr (BN == 128) {
                int kk = t >> 5, n4 = (t & 31) * 4;
                *(float4*)&Bs[kk][n4] = *(const float4*)(Bm + (size_t)(k0 + kk) * N + colBase + n4);
            } else { // BN == 64
                if (t < 128) {
                    int kk = t >> 4, n4 = (t & 15) * 4;
                    *(float4*)&Bs[kk][n4] = *(const float4*)(Bm + (size_t)(k0 + kk) * N + colBase + n4);
                }
            }
        }
        __syncthreads();
        #pragma unroll
        for (int kk = 0; kk < BK; kk++) {
            float a[TM], bb[TN];
            *(float4*)&a[0] = *(const float4*)&As[kk][ty * TM];
            *(float4*)&a[4] = *(const float4*)&As[kk][ty * TM + 4];
            *(float4*)&bb[0] = *(const float4*)&Bs[kk][tx * TN];
            if constexpr (TN == 8) *(float4*)&bb[4] = *(const float4*)&Bs[kk][tx * TN + 4];
            #pragma unroll
            for (int i = 0; i < TM; i++)
                #pragma unroll
                for (int j = 0; j < TN; j++)
                    acc[i][j] = fmaf(a[i], bb[j], acc[i][j]);
        }
        __syncthreads();
    }

    const int cb = colBase + tx * TN;
    #pragma unroll
    for (int i = 0; i < TM; i++) {
        int row = rowBase + ty * TM + i;
        #pragma unroll
        for (int j = 0; j < TN; j += 4) {
            int col = cb + j;
            float4 vv = make_float4(acc[i][j], acc[i][j+1], acc[i][j+2], acc[i][j+3]);
            if (bias) {
                float4 b4 = *(const float4*)(bias + col);
                vv.x += b4.x; vv.y += b4.y; vv.z += b4.z; vv.w += b4.w;
            }
            if constexpr (EPI == 1) {
                vv.x = fmaxf(vv.x, 0.f); vv.y = fmaxf(vv.y, 0.f);
                vv.z = fmaxf(vv.z, 0.f); vv.w = fmaxf(vv.w, 0.f);
            }
            if constexpr (EPI == 2) {
                float4 rr = *(const float4*)(Res + (size_t)row * N + col);
                vv.x += rr.x; vv.y += rr.y; vv.z += rr.z; vv.w += rr.w;
            }
            if constexpr (EPI == 3) {
                int b_ = row / Ss, s_ = row - b_ * Ss;
                int h_ = col / Dd, d_ = col - h_ * Dd;
                *(float4*)(C + (((size_t)b_ * Hh + h_) * Ss + s_) * Dd + d_) = vv;
            } else if constexpr (EPI == 4) {
                int b_ = bz / Hh, h_ = bz - b_ * Hh;
                *(float4*)(C + ((size_t)b_ * Ss + row) * Ee + h_ * Dd + col) = vv;
            } else {
                *(float4*)(C + (size_t)row * N + col) = vv;
            }
        }
    }
}

// ---------------- orchestration ----------------
extern "C" void kernel_launch(void* const* d_in, const int* in_sizes, int n_in,
                              void* d_out, int out_size)
{
    const float* x    = (const float*)d_in[0];
    const int*   mask = (const int*)  d_in[1];
    const float* wq   = (const float*)d_in[2];
    const float* bq   = (const float*)d_in[3];
    const float* wk   = (const float*)d_in[4];
    const float* bk   = (const float*)d_in[5];
    const float* wv   = (const float*)d_in[6];
    const float* bv   = (const float*)d_in[7];
    const float* wo   = (const float*)d_in[8];
    const float* bo   = (const float*)d_in[9];
    const float* w1   = (const float*)d_in[10];
    const float* b1   = (const float*)d_in[11];
    const float* w2   = (const float*)d_in[12];
    const float* b2   = (const float*)d_in[13];
    const float* ln1w = (const float*)d_in[14];
    const float* ln1b = (const float*)d_in[15];
    const float* ln2w = (const float*)d_in[16];
    const float* ln2b = (const float*)d_in[17];
    float* out = (float*)d_out;

    float *nx, *q, *k, *v, *vals, *x1, *hbuf, *sc;
    cudaGetSymbolAddress((void**)&nx,   g_nx);
    cudaGetSymbolAddress((void**)&q,    g_q);
    cudaGetSymbolAddress((void**)&k,    g_k);
    cudaGetSymbolAddress((void**)&v,    g_v);
    cudaGetSymbolAddress((void**)&vals, g_vals);
    cudaGetSymbolAddress((void**)&x1,   g_x1);
    cudaGetSymbolAddress((void**)&hbuf, g_h);
    cudaGetSymbolAddress((void**)&sc,   g_scores);

    // 1. LN1
    ln_kernel<<<Mtok, 256>>>(x, ln1w, ln1b, nx);

    // 2. QKV projections: [4096,1024] x [1024,1024]^T, scatter to [B,H,S,D]
    {
        dim3 g(Ee / 128, Mtok / 128, 1);
        gemm_kernel<true, 3, 128, 8><<<g, 256>>>(nx, wq, bq, nullptr, q, Mtok, Ee, Ee, 0, 0, 0);
        gemm_kernel<true, 3, 128, 8><<<g, 256>>>(nx, wk, bk, nullptr, k, Mtok, Ee, Ee, 0, 0, 0);
        gemm_kernel<true, 3, 128, 8><<<g, 256>>>(nx, wv, bv, nullptr, v, Mtok, Ee, Ee, 0, 0, 0);
    }

    // 3. scores = Q @ K^T per (b,h): [2048,64] x [2048,64]^T
    {
        dim3 g(Ss / 128, Ss / 128, Bb * Hh);
        gemm_kernel<true, 0, 128, 8><<<g, 256>>>(q, k, nullptr, nullptr, sc,
                                                 Ss, Ss, Dd,
                                                 (size_t)Ss * Dd, (size_t)Ss * Dd, (size_t)Ss * Ss);
    }

    // 4. softmax (scale + mask fused)
    softmax_kernel<<<Bb * Hh * Ss, 256>>>(sc, mask);

    // 5. vals = P @ V per (b,h): [2048,2048] x [2048,64], scatter to [B,S,E]
    {
        dim3 g(1, Ss / 128, Bb * Hh);
        gemm_kernel<false, 4, 64, 4><<<g, 256>>>(sc, v, nullptr, nullptr, vals,
                                                 Ss, Dd, Ss,
                                                 (size_t)Ss * Ss, (size_t)Ss * Dd, 0);
    }

    // 6. O projection + residual: x1 = x + vals @ wo^T + bo
    {
        dim3 g(Ee / 128, Mtok / 128, 1);
        gemm_kernel<true, 2, 128, 8><<<g, 256>>>(vals, wo, bo, x, x1, Mtok, Ee, Ee, 0, 0, 0);
    }

    // 7. LN2
    ln_kernel<<<Mtok, 256>>>(x1, ln2w, ln2b, nx);

    // 8. FFN1: h = relu(nx @ w1^T + b1)  [4096,1024] x [4096,1024]^T
    {
        dim3 g(Ff / 128, Mtok / 128, 1);
        gemm_kernel<true, 1, 128, 8><<<g, 256>>>(nx, w1, b1, nullptr, hbuf, Mtok, Ff, Ee, 0, 0, 0);
    }

    // 9. FFN2: out = x1 + h @ w2^T + b2  [4096,4096] x [1024,4096]^T
    {
        dim3 g(Ee / 128, Mtok / 128, 1);
        gemm_kernel<true, 2, 128, 8><<<g, 256>>>(hbuf, w2, b2, x1, out, Mtok, Ee, Ff, 0, 0, 0);
    }
}

// round 3
// speedup vs baseline: 2.2445x; 2.2445x over previous
#include <cuda_runtime.h>
#include <math.h>
#include <stdint.h>

// ---------------- problem constants ----------------
constexpr int   Bb   = 2;
constexpr int   Ss   = 2048;
constexpr int   Ee   = 1024;
constexpr int   Hh   = 16;
constexpr int   Dd   = 64;
constexpr int   Ff   = 4096;
constexpr int   Mtok = Bb * Ss;
constexpr float EPSc  = 1e-5f;
constexpr float SCALE = 0.125f;

// ---------------- scratch ----------------
__device__ float g_nx  [(size_t)Mtok * Ee];
__device__ float g_q   [(size_t)Mtok * Ee];   // [B,H,S,D]
__device__ float g_k   [(size_t)Mtok * Ee];   // [B,H,S,D]
__device__ float g_v   [(size_t)Mtok * Ee];   // [B,H,D,S]  (transposed!)
__device__ float g_vals[(size_t)Mtok * Ee];   // [B,S,E]
__device__ float g_x1  [(size_t)Mtok * Ee];
__device__ float g_h   [(size_t)Mtok * Ff];
__device__ float g_scores[(size_t)Bb * Hh * Ss * Ss];

// ---------------- reductions ----------------
__device__ __forceinline__ float warpSum(float v) {
    #pragma unroll
    for (int o = 16; o; o >>= 1) v += __shfl_xor_sync(0xFFFFFFFFu, v, o);
    return v;
}
__device__ __forceinline__ float warpMax(float v) {
    #pragma unroll
    for (int o = 16; o; o >>= 1) v = fmaxf(v, __shfl_xor_sync(0xFFFFFFFFu, v, o));
    return v;
}
__device__ __forceinline__ float blockSum(float v, float* sh, float* bc) {
    int lane = threadIdx.x & 31, wid = threadIdx.x >> 5;
    v = warpSum(v);
    if (!lane) sh[wid] = v;
    __syncthreads();
    if (wid == 0) {
        v = (lane < 8) ? sh[lane] : 0.f;
        v = warpSum(v);
        if (!lane) *bc = v;
    }
    __syncthreads();
    return *bc;
}
__device__ __forceinline__ float blockMax(float v, float* sh, float* bc) {
    int lane = threadIdx.x & 31, wid = threadIdx.x >> 5;
    v = warpMax(v);
    if (!lane) sh[wid] = v;
    __syncthreads();
    if (wid == 0) {
        v = (lane < 8) ? sh[lane] : -3.4e38f;
        v = warpMax(v);
        if (!lane) *bc = v;
    }
    __syncthreads();
    return *bc;
}

// ---------------- LayerNorm (unbiased var, /(std+eps)) ----------------
__global__ void ln_kernel(const float* __restrict__ x, const float* __restrict__ w,
                          const float* __restrict__ b, float* __restrict__ out)
{
    __shared__ float sh[32];
    __shared__ float bc;
    const int row = blockIdx.x, t = threadIdx.x;
    float4 v = *(const float4*)(x + (size_t)row * Ee + t * 4);
    float mean = blockSum(v.x + v.y + v.z + v.w, sh, &bc) * (1.f / Ee);
    float dx0 = v.x - mean, dx1 = v.y - mean, dx2 = v.z - mean, dx3 = v.w - mean;
    float var = blockSum(dx0*dx0 + dx1*dx1 + dx2*dx2 + dx3*dx3, sh, &bc) * (1.f / (Ee - 1));
    float r = 1.f / (sqrtf(var) + EPSc);
    float4 wv = *(const float4*)(w + t * 4);
    float4 bv = *(const float4*)(b + t * 4);
    float4 o;
    o.x = wv.x * dx0 * r + bv.x;
    o.y = wv.y * dx1 * r + bv.y;
    o.z = wv.z * dx2 * r + bv.z;
    o.w = wv.w * dx3 * r + bv.w;
    *(float4*)(out + (size_t)row * Ee + t * 4) = o;
}

// ---------------- softmax (scale + mask fused, in place) ----------------
__global__ void softmax_kernel(float* __restrict__ sc, const int* __restrict__ mask)
{
    __shared__ float sh[32];
    __shared__ float bc;
    const size_t row = blockIdx.x;
    const int t = threadIdx.x;
    float* p = sc + row * (size_t)Ss;
    const int b_ = (int)(row / ((size_t)Hh * Ss));
    const int s_ = (int)(row % Ss);
    const int* mrow = mask + ((size_t)b_ * Ss + s_) * Ss;

    float v[8];
    #pragma unroll
    for (int u = 0; u < 2; u++) {
        int idx = u * 1024 + t * 4;
        float4 sv = *(const float4*)(p + idx);
        int4   mv = *(const int4*)(mrow + idx);
        v[u*4+0] = mv.x ? sv.x * SCALE : -INFINITY;
        v[u*4+1] = mv.y ? sv.y * SCALE : -INFINITY;
        v[u*4+2] = mv.z ? sv.z * SCALE : -INFINITY;
        v[u*4+3] = mv.w ? sv.w * SCALE : -INFINITY;
    }
    float mx = v[0];
    #pragma unroll
    for (int i = 1; i < 8; i++) mx = fmaxf(mx, v[i]);
    mx = blockMax(mx, sh, &bc);
    float sum = 0.f;
    #pragma unroll
    for (int i = 0; i < 8; i++) { v[i] = __expf(v[i] - mx); sum += v[i]; }
    sum = blockSum(sum, sh, &bc);
    float inv = 1.f / sum;
    #pragma unroll
    for (int u = 0; u < 2; u++) {
        int idx = u * 1024 + t * 4;
        *(float4*)(p + idx) = make_float4(v[u*4+0]*inv, v[u*4+1]*inv, v[u*4+2]*inv, v[u*4+3]*inv);
    }
}

// ---------------- tf32 tensor-core GEMM ----------------
// C[m,n] = sum_k A[m,k] * B[n,k]   (B always [N,K] row-major; row stride = K)
// EPI: 0=plain(+bias if nonnull), 1=bias+relu, 2=bias+residual,
//      3=bias+scatter [B,H,S,D], 4=scatter vals [B,S,E], 5=bias+scatter V^T [B,H,D,S]
__device__ __forceinline__ float to_tf32(float x) {
    float r; asm("cvt.rna.tf32.f32 %0, %1;" : "=f"(r) : "f"(x)); return r;
}
__device__ __forceinline__ void ldsm4(uint32_t& r0, uint32_t& r1, uint32_t& r2, uint32_t& r3,
                                      const float* p) {
    uint32_t a = (uint32_t)__cvta_generic_to_shared(p);
    asm volatile("ldmatrix.sync.aligned.m8n8.x4.shared.b16 {%0,%1,%2,%3}, [%4];"
                 : "=r"(r0), "=r"(r1), "=r"(r2), "=r"(r3) : "r"(a));
}
__device__ __forceinline__ void mma_tf32(float* c, const uint32_t* a, const uint32_t* b) {
    asm volatile("mma.sync.aligned.m16n8k8.row.col.f32.tf32.tf32.f32 "
                 "{%0,%1,%2,%3}, {%4,%5,%6,%7}, {%8,%9}, {%0,%1,%2,%3};"
                 : "+f"(c[0]), "+f"(c[1]), "+f"(c[2]), "+f"(c[3])
                 : "r"(a[0]), "r"(a[1]), "r"(a[2]), "r"(a[3]), "r"(b[0]), "r"(b[1]));
}

constexpr int BM = 128, BK = 16, LDSD = BK + 4;   // stride 20 floats: conflict-free ldmatrix

template<int BN, int EPI>
__global__ void __launch_bounds__((BM/32)*(BN/32)*32, 1)
gemm_tf32(const float* __restrict__ A, const float* __restrict__ Bm,
          const float* __restrict__ bias, const float* __restrict__ Res,
          float* __restrict__ C, int M, int N, int K,
          size_t sA, size_t sB, size_t sC)
{
    constexpr int NWN = BN / 32;
    constexpr int NT  = (BM/32) * NWN * 32;
    constexpr int NA4 = (BM * BK / 4) / NT;
    constexpr int NB4 = (BN * BK / 4) / NT;

    __shared__ __align__(16) float As[2][BM][LDSD];
    __shared__ __align__(16) float Bs[2][BN][LDSD];

    const int bz = blockIdx.z;
    A  += (size_t)bz * sA;
    Bm += (size_t)bz * sB;
    C  += (size_t)bz * sC;

    const int tid = threadIdx.x, lane = tid & 31, warp = tid >> 5;
    const int wm = warp / NWN, wn = warp % NWN;
    const int rowBase = blockIdx.y * BM, colBase = blockIdx.x * BN;

    float acc[2][4][4];
    #pragma unroll
    for (int i = 0; i < 2; i++)
        #pragma unroll
        for (int j = 0; j < 4; j++)
            #pragma unroll
            for (int l = 0; l < 4; l++) acc[i][j][l] = 0.f;

    const int ntk = K / BK;
    float4 ra[NA4], rb[NB4];

    // initial stage load
    #pragma unroll
    for (int i = 0; i < NA4; i++) {
        int idx = tid + i * NT; int r = idx >> 2, c = (idx & 3) << 2;
        ra[i] = *(const float4*)(A + (size_t)(rowBase + r) * K + c);
    }
    #pragma unroll
    for (int i = 0; i < NB4; i++) {
        int idx = tid + i * NT; int r = idx >> 2, c = (idx & 3) << 2;
        rb[i] = *(const float4*)(Bm + (size_t)(colBase + r) * K + c);
    }
    #pragma unroll
    for (int i = 0; i < NA4; i++) {
        int idx = tid + i * NT; int r = idx >> 2, c = (idx & 3) << 2;
        float4 v = ra[i];
        *(float4*)&As[0][r][c] = make_float4(to_tf32(v.x), to_tf32(v.y), to_tf32(v.z), to_tf32(v.w));
    }
    #pragma unroll
    for (int i = 0; i < NB4; i++) {
        int idx = tid + i * NT; int r = idx >> 2, c = (idx & 3) << 2;
        float4 v = rb[i];
        *(float4*)&Bs[0][r][c] = make_float4(to_tf32(v.x), to_tf32(v.y), to_tf32(v.z), to_tf32(v.w));
    }
    __syncthreads();

    const int mi = lane >> 3, rr = lane & 7;

    for (int kt = 0; kt < ntk; kt++) {
        const int buf = kt & 1;
        if (kt + 1 < ntk) {
            const int k0 = (kt + 1) * BK;
            #pragma unroll
            for (int i = 0; i < NA4; i++) {
                int idx = tid + i * NT; int r = idx >> 2, c = (idx & 3) << 2;
                ra[i] = *(const float4*)(A + (size_t)(rowBase + r) * K + k0 + c);
            }
            #pragma unroll
            for (int i = 0; i < NB4; i++) {
                int idx = tid + i * NT; int r = idx >> 2, c = (idx & 3) << 2;
                rb[i] = *(const float4*)(Bm + (size_t)(colBase + r) * K + k0 + c);
            }
        }
        #pragma unroll
        for (int ks = 0; ks < 2; ks++) {
            const int ko = ks * 8;
            uint32_t a[2][4], b[4][2];
            #pragma unroll
            for (int mt = 0; mt < 2; mt++) {
                const float* p = &As[buf][wm*32 + mt*16 + (mi & 1)*8 + rr][ko + ((mi >> 1) & 1)*4];
                ldsm4(a[mt][0], a[mt][1], a[mt][2], a[mt][3], p);
            }
            #pragma unroll
            for (int pq = 0; pq < 2; pq++) {
                const float* p = &Bs[buf][wn*32 + pq*16 + ((mi >> 1) & 1)*8 + rr][ko + (mi & 1)*4];
                ldsm4(b[2*pq][0], b[2*pq][1], b[2*pq+1][0], b[2*pq+1][1], p);
            }
            #pragma unroll
            for (int mt = 0; mt < 2; mt++)
                #pragma unroll
                for (int nt = 0; nt < 4; nt++)
                    mma_tf32(acc[mt][nt], a[mt], b[nt]);
        }
        if (kt + 1 < ntk) {
            const int nb = buf ^ 1;
            #pragma unroll
            for (int i = 0; i < NA4; i++) {
                int idx = tid + i * NT; int r = idx >> 2, c = (idx & 3) << 2;
                float4 v = ra[i];
                *(float4*)&As[nb][r][c] = make_float4(to_tf32(v.x), to_tf32(v.y), to_tf32(v.z), to_tf32(v.w));
            }
            #pragma unroll
            for (int i = 0; i < NB4; i++) {
                int idx = tid + i * NT; int r = idx >> 2, c = (idx & 3) << 2;
                float4 v = rb[i];
                *(float4*)&Bs[nb][r][c] = make_float4(to_tf32(v.x), to_tf32(v.y), to_tf32(v.z), to_tf32(v.w));
            }
        }
        __syncthreads();
    }

    // ---- epilogue ----
    #pragma unroll
    for (int mt = 0; mt < 2; mt++)
        #pragma unroll
        for (int half = 0; half < 2; half++) {
            const int row = rowBase + wm*32 + mt*16 + (lane >> 2) + half*8;
            #pragma unroll
            for (int nt = 0; nt < 4; nt++) {
                const int col = colBase + wn*32 + nt*8 + (lane & 3)*2;
                float v0 = acc[mt][nt][half*2 + 0];
                float v1 = acc[mt][nt][half*2 + 1];
                if (bias) {
                    float2 bb = *(const float2*)(bias + col);
                    v0 += bb.x; v1 += bb.y;
                }
                if constexpr (EPI == 1) { v0 = fmaxf(v0, 0.f); v1 = fmaxf(v1, 0.f); }
                if constexpr (EPI == 2) {
                    float2 r2 = *(const float2*)(Res + (size_t)row * N + col);
                    v0 += r2.x; v1 += r2.y;
                }
                if constexpr (EPI == 3) {
                    int b_ = row / Ss, s_ = row - b_ * Ss;
                    int h_ = col / Dd, d_ = col - h_ * Dd;
                    *(float2*)(C + (((size_t)b_ * Hh + h_) * Ss + s_) * Dd + d_) = make_float2(v0, v1);
                } else if constexpr (EPI == 5) {
                    int b_ = row / Ss, s_ = row - b_ * Ss;
                    int h_ = col / Dd, d_ = col - h_ * Dd;
                    float* pp = C + (((size_t)b_ * Hh + h_) * Dd + d_) * Ss + s_;
                    pp[0]  = v0;
                    pp[Ss] = v1;
                } else if constexpr (EPI == 4) {
                    int b_ = bz / Hh, h_ = bz - b_ * Hh;
                    *(float2*)(C + ((size_t)b_ * Ss + row) * Ee + h_ * Dd + col) = make_float2(v0, v1);
                } else {
                    *(float2*)(C + (size_t)row * N + col) = make_float2(v0, v1);
                }
            }
        }
}

// ---------------- orchestration ----------------
extern "C" void kernel_launch(void* const* d_in, const int* in_sizes, int n_in,
                              void* d_out, int out_size)
{
    const float* x    = (const float*)d_in[0];
    const int*   mask = (const int*)  d_in[1];
    const float* wq   = (const float*)d_in[2];
    const float* bq   = (const float*)d_in[3];
    const float* wk   = (const float*)d_in[4];
    const float* bk   = (const float*)d_in[5];
    const float* wv   = (const float*)d_in[6];
    const float* bv   = (const float*)d_in[7];
    const float* wo   = (const float*)d_in[8];
    const float* bo   = (const float*)d_in[9];
    const float* w1   = (const float*)d_in[10];
    const float* b1   = (const float*)d_in[11];
    const float* w2   = (const float*)d_in[12];
    const float* b2   = (const float*)d_in[13];
    const float* ln1w = (const float*)d_in[14];
    const float* ln1b = (const float*)d_in[15];
    const float* ln2w = (const float*)d_in[16];
    const float* ln2b = (const float*)d_in[17];
    float* out = (float*)d_out;

    float *nx, *q, *k, *v, *vals, *x1, *hbuf, *sc;
    cudaGetSymbolAddress((void**)&nx,   g_nx);
    cudaGetSymbolAddress((void**)&q,    g_q);
    cudaGetSymbolAddress((void**)&k,    g_k);
    cudaGetSymbolAddress((void**)&v,    g_v);
    cudaGetSymbolAddress((void**)&vals, g_vals);
    cudaGetSymbolAddress((void**)&x1,   g_x1);
    cudaGetSymbolAddress((void**)&hbuf, g_h);
    cudaGetSymbolAddress((void**)&sc,   g_scores);

    // 1. LN1
    ln_kernel<<<Mtok, 256>>>(x, ln1w, ln1b, nx);

    // 2. QKV projections (V stored transposed [B,H,D,S])
    {
        dim3 g(Ee / 128, Mtok / 128, 1);
        gemm_tf32<128, 3><<<g, 512>>>(nx, wq, bq, nullptr, q, Mtok, Ee, Ee, 0, 0, 0);
        gemm_tf32<128, 3><<<g, 512>>>(nx, wk, bk, nullptr, k, Mtok, Ee, Ee, 0, 0, 0);
        gemm_tf32<128, 5><<<g, 512>>>(nx, wv, bv, nullptr, v, Mtok, Ee, Ee, 0, 0, 0);
    }

    // 3. scores = Q @ K^T per (b,h)
    {
        dim3 g(Ss / 128, Ss / 128, Bb * Hh);
        gemm_tf32<128, 0><<<g, 512>>>(q, k, nullptr, nullptr, sc, Ss, Ss, Dd,
                                      (size_t)Ss * Dd, (size_t)Ss * Dd, (size_t)Ss * Ss);
    }

    // 4. softmax
    softmax_kernel<<<Bb * Hh * Ss, 256>>>(sc, mask);

    // 5. vals = P @ V^T-as-[D,S]: TRANSB GEMM, N=64, scatter to [B,S,E]
    {
        dim3 g(Dd / 64, Ss / 128, Bb * Hh);
        gemm_tf32<64, 4><<<g, 256>>>(sc, v, nullptr, nullptr, vals, Ss, Dd, Ss,
                                     (size_t)Ss * Ss, (size_t)Dd * Ss, 0);
    }

    // 6. O projection + residual
    {
        dim3 g(Ee / 128, Mtok / 128, 1);
        gemm_tf32<128, 2><<<g, 512>>>(vals, wo, bo, x, x1, Mtok, Ee, Ee, 0, 0, 0);
    }

    // 7. LN2
    ln_kernel<<<Mtok, 256>>>(x1, ln2w, ln2b, nx);

    // 8. FFN1 (relu)
    {
        dim3 g(Ff / 128, Mtok / 128, 1);
        gemm_tf32<128, 1><<<g, 512>>>(nx, w1, b1, nullptr, hbuf, Mtok, Ff, Ee, 0, 0, 0);
    }

    // 9. FFN2 + residual
    {
        dim3 g(Ee / 128, Mtok / 128, 1);
        gemm_tf32<128, 2><<<g, 512>>>(hbuf, w2, b2, x1, out, Mtok, Ee, Ff, 0, 0, 0);
    }
}

// round 7
// speedup vs baseline: 2.6638x; 1.1868x over previous
#include <cuda_runtime.h>
#include <math.h>
#include <stdint.h>

// ---------------- problem constants ----------------
constexpr int   Bb   = 2;
constexpr int   Ss   = 2048;
constexpr int   Ee   = 1024;
constexpr int   Hh   = 16;
constexpr int   Dd   = 64;
constexpr int   Ff   = 4096;
constexpr int   Mtok = Bb * Ss;
constexpr float EPSc  = 1e-5f;
constexpr float SCALE = 0.125f;

// ---------------- scratch ----------------
__device__ float g_nx  [(size_t)Mtok * Ee];
__device__ float g_q   [(size_t)Mtok * Ee];   // [B,H,S,D]
__device__ float g_k   [(size_t)Mtok * Ee];   // [B,H,S,D]
__device__ float g_v   [(size_t)Mtok * Ee];   // [B,H,D,S]  (transposed)
__device__ float g_vals[(size_t)Mtok * Ee];   // [B,S,E]
__device__ float g_x1  [(size_t)Mtok * Ee];
__device__ float g_h   [(size_t)Mtok * Ff];

// ---------------- reductions ----------------
__device__ __forceinline__ float warpSum(float v) {
    #pragma unroll
    for (int o = 16; o; o >>= 1) v += __shfl_xor_sync(0xFFFFFFFFu, v, o);
    return v;
}
__device__ __forceinline__ float blockSum(float v, float* sh, float* bc) {
    int lane = threadIdx.x & 31, wid = threadIdx.x >> 5;
    v = warpSum(v);
    if (!lane) sh[wid] = v;
    __syncthreads();
    if (wid == 0) {
        v = (lane < 8) ? sh[lane] : 0.f;
        v = warpSum(v);
        if (!lane) *bc = v;
    }
    __syncthreads();
    return *bc;
}

// ---------------- LayerNorm ----------------
__global__ void ln_kernel(const float* __restrict__ x, const float* __restrict__ w,
                          const float* __restrict__ b, float* __restrict__ out)
{
    __shared__ float sh[32];
    __shared__ float bc;
    const int row = blockIdx.x, t = threadIdx.x;
    float4 v = *(const float4*)(x + (size_t)row * Ee + t * 4);
    float mean = blockSum(v.x + v.y + v.z + v.w, sh, &bc) * (1.f / Ee);
    float dx0 = v.x - mean, dx1 = v.y - mean, dx2 = v.z - mean, dx3 = v.w - mean;
    float var = blockSum(dx0*dx0 + dx1*dx1 + dx2*dx2 + dx3*dx3, sh, &bc) * (1.f / (Ee - 1));
    float r = 1.f / (sqrtf(var) + EPSc);
    float4 wv = *(const float4*)(w + t * 4);
    float4 bv = *(const float4*)(b + t * 4);
    float4 o;
    o.x = wv.x * dx0 * r + bv.x;
    o.y = wv.y * dx1 * r + bv.y;
    o.z = wv.z * dx2 * r + bv.z;
    o.w = wv.w * dx3 * r + bv.w;
    *(float4*)(out + (size_t)row * Ee + t * 4) = o;
}

// ---------------- tf32 helpers ----------------
__device__ __forceinline__ float to_tf32(float x) {
    float r; asm("cvt.rna.tf32.f32 %0, %1;" : "=f"(r) : "f"(x)); return r;
}
__device__ __forceinline__ void ldsm4(uint32_t& r0, uint32_t& r1, uint32_t& r2, uint32_t& r3,
                                      const float* p) {
    uint32_t a = (uint32_t)__cvta_generic_to_shared(p);
    asm volatile("ldmatrix.sync.aligned.m8n8.x4.shared.b16 {%0,%1,%2,%3}, [%4];"
                 : "=r"(r0), "=r"(r1), "=r"(r2), "=r"(r3) : "r"(a));
}
__device__ __forceinline__ void mma_tf32(float* c, const uint32_t* a, const uint32_t* b) {
    asm volatile("mma.sync.aligned.m16n8k8.row.col.f32.tf32.tf32.f32 "
                 "{%0,%1,%2,%3}, {%4,%5,%6,%7}, {%8,%9}, {%0,%1,%2,%3};"
                 : "+f"(c[0]), "+f"(c[1]), "+f"(c[2]), "+f"(c[3])
                 : "r"(a[0]), "r"(a[1]), "r"(a[2]), "r"(a[3]), "r"(b[0]), "r"(b[1]));
}

// ---------------- flash attention: Br=64, Bc=64, 4 warps ----------------
constexpr int FLD = 68;  // smem row stride (floats)

__global__ void __launch_bounds__(128)
flash_kernel(const float* __restrict__ q, const float* __restrict__ k,
             const float* __restrict__ v, const int* __restrict__ mask,
             float* __restrict__ vals)
{
    extern __shared__ float sm[];
    float* Ksm = sm;                 // [64][FLD]
    float* Vsm = Ksm + 64 * FLD;     // [64][FLD]
    float* Psm = Vsm + 64 * FLD;     // [64][FLD]  (also Q staging)

    const int bh = blockIdx.y;
    const int b_ = bh >> 4, h_ = bh & 15;
    const int q0 = blockIdx.x * 64;
    const int tid = threadIdx.x, lane = tid & 31, w = tid >> 5;
    const int mi = lane >> 3, rr = lane & 7;

    const float* Qp = q + ((size_t)bh * Ss + q0) * Dd;
    const float* Kp = k + (size_t)bh * Ss * Dd;
    const float* Vp = v + (size_t)bh * Dd * Ss;   // [D][S]

    // stage Q tile into Psm (tf32), pull A-fragments to registers
    #pragma unroll
    for (int i = tid; i < 64 * 16; i += 128) {
        int r = i >> 4, c4 = (i & 15) << 2;
        float4 t = *(const float4*)(Qp + (size_t)r * Dd + c4);
        *(float4*)&Psm[r * FLD + c4] =
            make_float4(to_tf32(t.x), to_tf32(t.y), to_tf32(t.z), to_tf32(t.w));
    }
    __syncthreads();
    uint32_t qa[8][4];
    #pragma unroll
    for (int ks = 0; ks < 8; ks++) {
        const float* p = &Psm[(w*16 + (mi & 1)*8 + rr) * FLD + ks*8 + ((mi >> 1) & 1)*4];
        ldsm4(qa[ks][0], qa[ks][1], qa[ks][2], qa[ks][3], p);
    }

    float oacc[8][4];
    #pragma unroll
    for (int i = 0; i < 8; i++)
        #pragma unroll
        for (int j = 0; j < 4; j++) oacc[i][j] = 0.f;
    float mrun0 = -1e30f, mrun1 = -1e30f, lrun0 = 0.f, lrun1 = 0.f;

    const int r0 = q0 + w*16 + (lane >> 2);
    const int* mrow0 = mask + ((size_t)b_ * Ss + r0) * Ss;
    const int* mrow1 = mrow0 + 8 * (size_t)Ss;

    for (int it = 0; it < Ss / 64; it++) {
        const int kv0 = it * 64;
        // load K tile [s][d] and V^T tile [d][s] (tf32)
        #pragma unroll
        for (int i = tid; i < 64 * 16; i += 128) {
            int r = i >> 4, c4 = (i & 15) << 2;
            float4 t = *(const float4*)(Kp + (size_t)(kv0 + r) * Dd + c4);
            *(float4*)&Ksm[r * FLD + c4] =
                make_float4(to_tf32(t.x), to_tf32(t.y), to_tf32(t.z), to_tf32(t.w));
        }
        #pragma unroll
        for (int i = tid; i < 64 * 16; i += 128) {
            int r = i >> 4, c4 = (i & 15) << 2;
            float4 t = *(const float4*)(Vp + (size_t)r * Ss + kv0 + c4);
            *(float4*)&Vsm[r * FLD + c4] =
                make_float4(to_tf32(t.x), to_tf32(t.y), to_tf32(t.z), to_tf32(t.w));
        }
        __syncthreads();

        // scores = Q @ K^T  (per warp 16x64)
        float sacc[8][4];
        #pragma unroll
        for (int i = 0; i < 8; i++)
            #pragma unroll
            for (int j = 0; j < 4; j++) sacc[i][j] = 0.f;
        #pragma unroll
        for (int ks = 0; ks < 8; ks++) {
            uint32_t bf[8][2];
            #pragma unroll
            for (int pq = 0; pq < 4; pq++) {
                const float* p = &Ksm[(pq*16 + ((mi >> 1) & 1)*8 + rr) * FLD + ks*8 + (mi & 1)*4];
                ldsm4(bf[2*pq][0], bf[2*pq][1], bf[2*pq+1][0], bf[2*pq+1][1], p);
            }
            #pragma unroll
            for (int nt = 0; nt < 8; nt++) mma_tf32(sacc[nt], qa[ks], bf[nt]);
        }

        // scale + mask + online softmax
        float ml0 = -1e30f, ml1 = -1e30f;
        #pragma unroll
        for (int nt = 0; nt < 8; nt++) {
            int c = kv0 + nt*8 + (lane & 3)*2;
            int2 ma = *(const int2*)(mrow0 + c);
            int2 mb = *(const int2*)(mrow1 + c);
            sacc[nt][0] = ma.x ? sacc[nt][0] * SCALE : -1e30f;
            sacc[nt][1] = ma.y ? sacc[nt][1] * SCALE : -1e30f;
            sacc[nt][2] = mb.x ? sacc[nt][2] * SCALE : -1e30f;
            sacc[nt][3] = mb.y ? sacc[nt][3] * SCALE : -1e30f;
            ml0 = fmaxf(ml0, fmaxf(sacc[nt][0], sacc[nt][1]));
            ml1 = fmaxf(ml1, fmaxf(sacc[nt][2], sacc[nt][3]));
        }
        ml0 = fmaxf(ml0, __shfl_xor_sync(0xFFFFFFFFu, ml0, 1));
        ml0 = fmaxf(ml0, __shfl_xor_sync(0xFFFFFFFFu, ml0, 2));
        ml1 = fmaxf(ml1, __shfl_xor_sync(0xFFFFFFFFu, ml1, 1));
        ml1 = fmaxf(ml1, __shfl_xor_sync(0xFFFFFFFFu, ml1, 2));
        float mn0 = fmaxf(mrun0, ml0), mn1 = fmaxf(mrun1, ml1);
        float f0 = __expf(mrun0 - mn0), f1 = __expf(mrun1 - mn1);
        float ps0 = 0.f, ps1 = 0.f;
        #pragma unroll
        for (int nt = 0; nt < 8; nt++) {
            sacc[nt][0] = __expf(sacc[nt][0] - mn0);
            sacc[nt][1] = __expf(sacc[nt][1] - mn0);
            sacc[nt][2] = __expf(sacc[nt][2] - mn1);
            sacc[nt][3] = __expf(sacc[nt][3] - mn1);
            ps0 += sacc[nt][0] + sacc[nt][1];
            ps1 += sacc[nt][2] + sacc[nt][3];
        }
        ps0 += __shfl_xor_sync(0xFFFFFFFFu, ps0, 1);
        ps0 += __shfl_xor_sync(0xFFFFFFFFu, ps0, 2);
        ps1 += __shfl_xor_sync(0xFFFFFFFFu, ps1, 1);
        ps1 += __shfl_xor_sync(0xFFFFFFFFu, ps1, 2);
        lrun0 = lrun0 * f0 + ps0; lrun1 = lrun1 * f1 + ps1;
        mrun0 = mn0; mrun1 = mn1;
        #pragma unroll
        for (int nt = 0; nt < 8; nt++) {
            oacc[nt][0] *= f0; oacc[nt][1] *= f0;
            oacc[nt][2] *= f1; oacc[nt][3] *= f1;
        }
        // write P tile (tf32)
        {
            int pr = w*16 + (lane >> 2);
            #pragma unroll
            for (int nt = 0; nt < 8; nt++) {
                int c = nt*8 + (lane & 3)*2;
                *(float2*)&Psm[pr * FLD + c] =
                    make_float2(to_tf32(sacc[nt][0]), to_tf32(sacc[nt][1]));
                *(float2*)&Psm[(pr + 8) * FLD + c] =
                    make_float2(to_tf32(sacc[nt][2]), to_tf32(sacc[nt][3]));
            }
        }
        __syncthreads();

        // O += P @ V
        #pragma unroll
        for (int ks = 0; ks < 8; ks++) {
            uint32_t pa[4];
            {
                const float* p = &Psm[(w*16 + (mi & 1)*8 + rr) * FLD + ks*8 + ((mi >> 1) & 1)*4];
                ldsm4(pa[0], pa[1], pa[2], pa[3], p);
            }
            uint32_t bf[8][2];
            #pragma unroll
            for (int pq = 0; pq < 4; pq++) {
                const float* p = &Vsm[(pq*16 + ((mi >> 1) & 1)*8 + rr) * FLD + ks*8 + (mi & 1)*4];
                ldsm4(bf[2*pq][0], bf[2*pq][1], bf[2*pq+1][0], bf[2*pq+1][1], p);
            }
            #pragma unroll
            for (int nt = 0; nt < 8; nt++) mma_tf32(oacc[nt], pa, bf[nt]);
        }
        __syncthreads();
    }

    // epilogue: normalize and write to vals[B,S,E]
    float inv0 = 1.f / lrun0, inv1 = 1.f / lrun1;
    float* op = vals + ((size_t)b_ * Ss + r0) * Ee + h_ * Dd;
    #pragma unroll
    for (int nt = 0; nt < 8; nt++) {
        int c = nt*8 + (lane & 3)*2;
        *(float2*)(op + c) = make_float2(oacc[nt][0] * inv0, oacc[nt][1] * inv0);
        *(float2*)(op + (size_t)8 * Ee + c) = make_float2(oacc[nt][2] * inv1, oacc[nt][3] * inv1);
    }
}

// ---------------- tf32 dense GEMM ----------------
// C[m,n] = sum_k A[m,k] * B[n,k]; EPI: 1=bias+relu, 2=bias+residual,
// 3=bias+scatter [B,H,S,D], 5=bias+scatter V^T [B,H,D,S]
constexpr int BM = 128, BK = 16, LDSD = BK + 4;

template<int BN, int EPI>
__global__ void __launch_bounds__((BM/32)*(BN/32)*32, 1)
gemm_tf32(const float* __restrict__ A, const float* __restrict__ Bm,
          const float* __restrict__ bias, const float* __restrict__ Res,
          float* __restrict__ C, int M, int N, int K,
          size_t sA, size_t sB, size_t sC)
{
    constexpr int NWN = BN / 32;
    constexpr int NT  = (BM/32) * NWN * 32;
    constexpr int NA4 = (BM * BK / 4) / NT;
    constexpr int NB4 = (BN * BK / 4) / NT;

    __shared__ __align__(16) float As[2][BM][LDSD];
    __shared__ __align__(16) float Bs[2][BN][LDSD];

    const int bz = blockIdx.z;
    A  += (size_t)bz * sA;
    Bm += (size_t)bz * sB;
    C  += (size_t)bz * sC;

    const int tid = threadIdx.x, lane = tid & 31, warp = tid >> 5;
    const int wm = warp / NWN, wn = warp % NWN;
    const int rowBase = blockIdx.y * BM, colBase = blockIdx.x * BN;

    float acc[2][4][4];
    #pragma unroll
    for (int i = 0; i < 2; i++)
        #pragma unroll
        for (int j = 0; j < 4; j++)
            #pragma unroll
            for (int l = 0; l < 4; l++) acc[i][j][l] = 0.f;

    const int ntk = K / BK;
    float4 ra[NA4], rb[NB4];

    #pragma unroll
    for (int i = 0; i < NA4; i++) {
        int idx = tid + i * NT; int r = idx >> 2, c = (idx & 3) << 2;
        ra[i] = *(const float4*)(A + (size_t)(rowBase + r) * K + c);
    }
    #pragma unroll
    for (int i = 0; i < NB4; i++) {
        int idx = tid + i * NT; int r = idx >> 2, c = (idx & 3) << 2;
        rb[i] = *(const float4*)(Bm + (size_t)(colBase + r) * K + c);
    }
    #pragma unroll
    for (int i = 0; i < NA4; i++) {
        int idx = tid + i * NT; int r = idx >> 2, c = (idx & 3) << 2;
        float4 v = ra[i];
        *(float4*)&As[0][r][c] = make_float4(to_tf32(v.x), to_tf32(v.y), to_tf32(v.z), to_tf32(v.w));
    }
    #pragma unroll
    for (int i = 0; i < NB4; i++) {
        int idx = tid + i * NT; int r = idx >> 2, c = (idx & 3) << 2;
        float4 v = rb[i];
        *(float4*)&Bs[0][r][c] = make_float4(to_tf32(v.x), to_tf32(v.y), to_tf32(v.z), to_tf32(v.w));
    }
    __syncthreads();

    const int mi = lane >> 3, rr = lane & 7;

    for (int kt = 0; kt < ntk; kt++) {
        const int buf = kt & 1;
        if (kt + 1 < ntk) {
            const int k0 = (kt + 1) * BK;
            #pragma unroll
            for (int i = 0; i < NA4; i++) {
                int idx = tid + i * NT; int r = idx >> 2, c = (idx & 3) << 2;
                ra[i] = *(const float4*)(A + (size_t)(rowBase + r) * K + k0 + c);
            }
            #pragma unroll
            for (int i = 0; i < NB4; i++) {
                int idx = tid + i * NT; int r = idx >> 2, c = (idx & 3) << 2;
                rb[i] = *(const float4*)(Bm + (size_t)(colBase + r) * K + k0 + c);
            }
        }
        #pragma unroll
        for (int ks = 0; ks < 2; ks++) {
            const int ko = ks * 8;
            uint32_t a[2][4], b[4][2];
            #pragma unroll
            for (int mt = 0; mt < 2; mt++) {
                const float* p = &As[buf][wm*32 + mt*16 + (mi & 1)*8 + rr][ko + ((mi >> 1) & 1)*4];
                ldsm4(a[mt][0], a[mt][1], a[mt][2], a[mt][3], p);
            }
            #pragma unroll
            for (int pq = 0; pq < 2; pq++) {
                const float* p = &Bs[buf][wn*32 + pq*16 + ((mi >> 1) & 1)*8 + rr][ko + (mi & 1)*4];
                ldsm4(b[2*pq][0], b[2*pq][1], b[2*pq+1][0], b[2*pq+1][1], p);
            }
            #pragma unroll
            for (int mt = 0; mt < 2; mt++)
                #pragma unroll
                for (int nt = 0; nt < 4; nt++)
                    mma_tf32(acc[mt][nt], a[mt], b[nt]);
        }
        if (kt + 1 < ntk) {
            const int nb = buf ^ 1;
            #pragma unroll
            for (int i = 0; i < NA4; i++) {
                int idx = tid + i * NT; int r = idx >> 2, c = (idx & 3) << 2;
                float4 v = ra[i];
                *(float4*)&As[nb][r][c] = make_float4(to_tf32(v.x), to_tf32(v.y), to_tf32(v.z), to_tf32(v.w));
            }
            #pragma unroll
            for (int i = 0; i < NB4; i++) {
                int idx = tid + i * NT; int r = idx >> 2, c = (idx & 3) << 2;
                float4 v = rb[i];
                *(float4*)&Bs[nb][r][c] = make_float4(to_tf32(v.x), to_tf32(v.y), to_tf32(v.z), to_tf32(v.w));
            }
        }
        __syncthreads();
    }

    #pragma unroll
    for (int mt = 0; mt < 2; mt++)
        #pragma unroll
        for (int half = 0; half < 2; half++) {
            const int row = rowBase + wm*32 + mt*16 + (lane >> 2) + half*8;
            #pragma unroll
            for (int nt = 0; nt < 4; nt++) {
                const int col = colBase + wn*32 + nt*8 + (lane & 3)*2;
                float v0 = acc[mt][nt][half*2 + 0];
                float v1 = acc[mt][nt][half*2 + 1];
                if (bias) {
                    float2 bb = *(const float2*)(bias + col);
                    v0 += bb.x; v1 += bb.y;
                }
                if constexpr (EPI == 1) { v0 = fmaxf(v0, 0.f); v1 = fmaxf(v1, 0.f); }
                if constexpr (EPI == 2) {
                    float2 r2 = *(const float2*)(Res + (size_t)row * N + col);
                    v0 += r2.x; v1 += r2.y;
                }
                if constexpr (EPI == 3) {
                    int b_ = row / Ss, s_ = row - b_ * Ss;
                    int h_ = col / Dd, d_ = col - h_ * Dd;
                    *(float2*)(C + (((size_t)b_ * Hh + h_) * Ss + s_) * Dd + d_) = make_float2(v0, v1);
                } else if constexpr (EPI == 5) {
                    int b_ = row / Ss, s_ = row - b_ * Ss;
                    int h_ = col / Dd, d_ = col - h_ * Dd;
                    float* pp = C + (((size_t)b_ * Hh + h_) * Dd + d_) * Ss + s_;
                    pp[0]  = v0;
                    pp[Ss] = v1;
                } else {
                    *(float2*)(C + (size_t)row * N + col) = make_float2(v0, v1);
                }
            }
        }
}

// ---------------- orchestration ----------------
extern "C" void kernel_launch(void* const* d_in, const int* in_sizes, int n_in,
                              void* d_out, int out_size)
{
    const float* x    = (const float*)d_in[0];
    const int*   mask = (const int*)  d_in[1];
    const float* wq   = (const float*)d_in[2];
    const float* bq   = (const float*)d_in[3];
    const float* wk   = (const float*)d_in[4];
    const float* bk   = (const float*)d_in[5];
    const float* wv   = (const float*)d_in[6];
    const float* bv   = (const float*)d_in[7];
    const float* wo   = (const float*)d_in[8];
    const float* bo   = (const float*)d_in[9];
    const float* w1   = (const float*)d_in[10];
    const float* b1   = (const float*)d_in[11];
    const float* w2   = (const float*)d_in[12];
    const float* b2   = (const float*)d_in[13];
    const float* ln1w = (const float*)d_in[14];
    const float* ln1b = (const float*)d_in[15];
    const float* ln2w = (const float*)d_in[16];
    const float* ln2b = (const float*)d_in[17];
    float* out = (float*)d_out;

    float *nx, *q, *k, *v, *vals, *x1, *hbuf;
    cudaGetSymbolAddress((void**)&nx,   g_nx);
    cudaGetSymbolAddress((void**)&q,    g_q);
    cudaGetSymbolAddress((void**)&k,    g_k);
    cudaGetSymbolAddress((void**)&v,    g_v);
    cudaGetSymbolAddress((void**)&vals, g_vals);
    cudaGetSymbolAddress((void**)&x1,   g_x1);
    cudaGetSymbolAddress((void**)&hbuf, g_h);

    // idempotent, unconditional (no static state — harness rule)
    const int flash_smem = 3 * 64 * FLD * sizeof(float);
    cudaFuncSetAttribute(flash_kernel, cudaFuncAttributeMaxDynamicSharedMemorySize, flash_smem);

    // 1. LN1
    ln_kernel<<<Mtok, 256>>>(x, ln1w, ln1b, nx);

    // 2. QKV projections (V transposed to [B,H,D,S])
    {
        dim3 g(Ee / 128, Mtok / 128, 1);
        gemm_tf32<128, 3><<<g, 512>>>(nx, wq, bq, nullptr, q, Mtok, Ee, Ee, 0, 0, 0);
        gemm_tf32<128, 3><<<g, 512>>>(nx, wk, bk, nullptr, k, Mtok, Ee, Ee, 0, 0, 0);
        gemm_tf32<128, 5><<<g, 512>>>(nx, wv, bv, nullptr, v, Mtok, Ee, Ee, 0, 0, 0);
    }

    // 3-5. fused flash attention -> vals [B,S,E]
    {
        dim3 g(Ss / 64, Bb * Hh);
        flash_kernel<<<g, 128, flash_smem>>>(q, k, v, mask, vals);
    }

    // 6. O projection + residual
    {
        dim3 g(Ee / 128, Mtok / 128, 1);
        gemm_tf32<128, 2><<<g, 512>>>(vals, wo, bo, x, x1, Mtok, Ee, Ee, 0, 0, 0);
    }

    // 7. LN2
    ln_kernel<<<Mtok, 256>>>(x1, ln2w, ln2b, nx);

    // 8. FFN1 (relu)
    {
        dim3 g(Ff / 128, Mtok / 128, 1);
        gemm_tf32<128, 1><<<g, 512>>>(nx, w1, b1, nullptr, hbuf, Mtok, Ff, Ee, 0, 0, 0);
    }

    // 9. FFN2 + residual
    {
        dim3 g(Ee / 128, Mtok / 128, 1);
        gemm_tf32<128, 2><<<g, 512>>>(hbuf, w2, b2, x1, out, Mtok, Ee, Ff, 0, 0, 0);
    }
}